// round 4
// baseline (speedup 1.0000x reference)
#include <cuda_runtime.h>
#include <math.h>

#define N_NODES 4096
#define KDIM    512
#define D_H     64
#define HEADS   8
#define MAXD    192
#define CH      64

typedef unsigned long long ull;

// ---------------- packed f32x2 helpers (Blackwell) ----------------
__device__ __forceinline__ ull pack2(float a) {
    ull r;
    asm("mov.b64 %0, {%1, %1};" : "=l"(r) : "f"(a));
    return r;
}
__device__ __forceinline__ void fma2(ull& d, ull a, ull b) {
    asm("fma.rn.f32x2 %0, %1, %2, %0;" : "+l"(d) : "l"(a), "l"(b));
}
__device__ __forceinline__ void unpack2(ull v, float& lo, float& hi) {
    asm("mov.b64 {%0, %1}, %2;" : "=f"(lo), "=f"(hi) : "l"(v));
}

// ---------------- scratch ----------------
__device__ float g_x [N_NODES * D_H];
__device__ float g_el[N_NODES * HEADS];
__device__ float g_er[N_NODES * HEADS];
__device__ float g_h1[N_NODES * D_H * HEADS];
__device__ float g_h2[N_NODES * D_H * HEADS];
__device__ int   g_cols[N_NODES * MAXD];
__device__ int   g_deg [N_NODES];

// ---------------- CSR build: warp per row, ordered ballot compaction ------
__global__ __launch_bounds__(256) void build_csr_kernel(const float* __restrict__ adj) {
    int warp = (blockIdx.x * blockDim.x + threadIdx.x) >> 5;
    int lane = threadIdx.x & 31;
    if (warp >= N_NODES) return;
    const float4* a = reinterpret_cast<const float4*>(adj + (size_t)warp * N_NODES);
    int* out = g_cols + warp * MAXD;
    int base = 0;
    for (int j0 = 0; j0 < N_NODES; j0 += 128) {
        float4 v = a[(j0 >> 2) + lane];
        float vv[4] = {v.x, v.y, v.z, v.w};
        #pragma unroll
        for (int c = 0; c < 4; c++) {
            unsigned m = __ballot_sync(0xffffffffu, vv[c] != 0.0f);
            if (vv[c] != 0.0f) {
                int pos = base + __popc(m & ((1u << lane) - 1u));
                if (pos < MAXD) out[pos] = j0 + lane * 4 + c;
            }
            base += __popc(m);
        }
    }
    if (lane == 0) g_deg[warp] = base < MAXD ? base : MAXD;
}

// ---- GEMM + attn projection: C[4096x64] = A[4096x512] @ B[512x64] --------
// BM=16, BN=64, BK=32, 128 threads, 256 blocks. 2x4 micro-tile per thread.
// Register-prefetch double buffer. Epilogue computes el/er.
__global__ __launch_bounds__(128) void gemm_proj_kernel(const float* __restrict__ A,
                                                        const float* __restrict__ B,
                                                        const float* __restrict__ al,
                                                        const float* __restrict__ ar,
                                                        float* __restrict__ C, int H) {
    __shared__ float As[16][33];
    __shared__ float Bs[32][64];
    int tid = threadIdx.x;
    int tx = tid & 15, ty = tid >> 4;          // ty 0..7 -> rows ty*2, ty*2+1
    int rowBase = blockIdx.x * 16;

    int arow = tid >> 3;                        // 0..15
    int ak4  = (tid & 7) << 2;                  // 0..28
    const float* Aptr = A + (size_t)(rowBase + arow) * KDIM + ak4;

    float4 a_n, b_n[4];
    a_n = *reinterpret_cast<const float4*>(Aptr);
    #pragma unroll
    for (int s = 0; s < 4; s++) {
        int idx = tid + 128 * s;
        b_n[s] = *reinterpret_cast<const float4*>(B + (size_t)(idx >> 4) * 64 + (idx & 15) * 4);
    }

    ull acc[2][2] = {{0ull, 0ull}, {0ull, 0ull}};

    for (int kt = 0; kt < KDIM; kt += 32) {
        As[arow][ak4+0] = a_n.x; As[arow][ak4+1] = a_n.y;
        As[arow][ak4+2] = a_n.z; As[arow][ak4+3] = a_n.w;
        #pragma unroll
        for (int s = 0; s < 4; s++) {
            int idx = tid + 128 * s;
            *reinterpret_cast<float4*>(&Bs[idx >> 4][(idx & 15) * 4]) = b_n[s];
        }
        __syncthreads();
        if (kt + 32 < KDIM) {
            a_n = *reinterpret_cast<const float4*>(Aptr + kt + 32);
            #pragma unroll
            for (int s = 0; s < 4; s++) {
                int idx = tid + 128 * s;
                b_n[s] = *reinterpret_cast<const float4*>(B + (size_t)(kt + 32 + (idx >> 4)) * 64 + (idx & 15) * 4);
            }
        }
        #pragma unroll
        for (int k = 0; k < 32; k++) {
            ull pa0 = pack2(As[ty*2][k]);
            ull pa1 = pack2(As[ty*2+1][k]);
            ulonglong2 bb = *reinterpret_cast<const ulonglong2*>(&Bs[k][tx*4]);
            fma2(acc[0][0], pa0, bb.x);
            fma2(acc[0][1], pa0, bb.y);
            fma2(acc[1][0], pa1, bb.x);
            fma2(acc[1][1], pa1, bb.y);
        }
        __syncthreads();
    }

    // write C; stage C tile into Bs rows 0..15, al/ar into Bs rows 16..31
    #pragma unroll
    for (int i = 0; i < 2; i++) {
        int r = ty*2 + i;
        ulonglong2 v; v.x = acc[i][0]; v.y = acc[i][1];
        *reinterpret_cast<ulonglong2*>(C + (size_t)(rowBase + r) * 64 + tx*4) = v;
        *reinterpret_cast<ulonglong2*>(&Bs[r][tx*4]) = v;
    }
    float* sAl = &Bs[16][0];                    // 64*H floats (max 512)
    float* sAr = &Bs[24][0];
    for (int idx = tid; idx < 64 * H; idx += 128) {
        sAl[idx] = al[idx];
        sAr[idx] = ar[idx];
    }
    __syncthreads();

    if (tid < 16 * H) {
        int r = (H == 8) ? (tid >> 3) : tid;
        int h = (H == 8) ? (tid & 7)  : 0;
        float sl = 0.f, sr = 0.f;
        #pragma unroll
        for (int d = 0; d < 64; d++) {
            float cv = Bs[r][d];
            sl += cv * sAl[d * H + h];
            sr += cv * sAr[d * H + h];
        }
        g_el[(rowBase + r) * H + h] = sl;
        g_er[(rowBase + r) * H + h] = sr;
    }
}

// ---------------- 8-head aggregation: block per node, 128 threads ----------
// thread = (h, q); direct LDG gather of x rows, pre-packed f32x2 weights.
__global__ __launch_bounds__(128) void agg8_kernel(const float* __restrict__ bias,
                                                   float* __restrict__ out, int act) {
    int i   = blockIdx.x;
    int tid = threadIdx.x;
    int h   = tid >> 4;
    int q   = tid & 15;

    __shared__ int   s_cols[CH];
    __shared__ float s_el[HEADS];
    __shared__ ull   s_w[CH][HEADS];

    if (tid < HEADS) s_el[tid] = g_el[i * HEADS + tid];
    int deg = g_deg[i];
    const int* cols = g_cols + (size_t)i * MAXD;
    const float* xq = g_x + q * 4;

    ull acc0 = 0ull, acc1 = 0ull;
    float sw = 0.f;

    for (int j0 = 0; j0 < deg; j0 += CH) {
        int cl = min(CH, deg - j0);
        if (tid < cl) s_cols[tid] = cols[j0 + tid];
        __syncthreads();
        for (int idx = tid; idx < cl * HEADS; idx += 128) {
            int jj = idx >> 3, hh = idx & 7;
            float s = s_el[hh] + g_er[s_cols[jj] * HEADS + hh];
            s = (s >= 0.f) ? s : 0.2f * s;
            s_w[jj][hh] = pack2(__expf(s));
        }
        __syncthreads();
        #pragma unroll 4
        for (int jj = 0; jj < cl; jj++) {
            ull pw = s_w[jj][h];
            ulonglong2 xv = *reinterpret_cast<const ulonglong2*>(xq + (size_t)s_cols[jj] * D_H);
            float wlo, whi;
            unpack2(pw, wlo, whi);
            fma2(acc0, pw, xv.x);
            fma2(acc1, pw, xv.y);
            sw += wlo;
        }
        __syncthreads();
    }

    float inv = 1.0f / fmaxf(sw, 1e-12f);
    float4 bv = *reinterpret_cast<const float4*>(bias + q * 4);
    float v0, v1, v2, v3;
    unpack2(acc0, v0, v1);
    unpack2(acc1, v2, v3);
    v0 = v0 * inv + bv.x; v1 = v1 * inv + bv.y;
    v2 = v2 * inv + bv.z; v3 = v3 * inv + bv.w;
    if (act) {
        v0 = (v0 > 0.f) ? v0 : expm1f(v0);
        v1 = (v1 > 0.f) ? v1 : expm1f(v1);
        v2 = (v2 > 0.f) ? v2 : expm1f(v2);
        v3 = (v3 > 0.f) ? v3 : expm1f(v3);
    }
    float4 ov = make_float4(v0, v1, v2, v3);
    *reinterpret_cast<float4*>(out + (size_t)i * (HEADS * D_H) + h * D_H + q * 4) = ov;
}

// ---------------- 1-head aggregation: block per node, 64 threads -----------
__global__ __launch_bounds__(64) void agg1_kernel(const float* __restrict__ bias,
                                                  float* __restrict__ out) {
    int i   = blockIdx.x;
    int tid = threadIdx.x;   // = d

    __shared__ int   s_cols[CH];
    __shared__ float s_w[CH];

    float eli = g_el[i];
    int deg = g_deg[i];
    const int* cols = g_cols + (size_t)i * MAXD;
    float acc = 0.f, sw = 0.f;

    for (int j0 = 0; j0 < deg; j0 += CH) {
        int cl = min(CH, deg - j0);
        if (tid < cl) {
            int c = cols[j0 + tid];
            s_cols[tid] = c;
            float s = eli + g_er[c];
            s = (s >= 0.f) ? s : 0.2f * s;
            s_w[tid] = __expf(s);
        }
        __syncthreads();
        #pragma unroll 4
        for (int jj = 0; jj < cl; jj++) {
            float wv = s_w[jj];
            acc += wv * g_x[(size_t)s_cols[jj] * D_H + tid];
            sw  += wv;
        }
        __syncthreads();
    }

    float v = acc / fmaxf(sw, 1e-12f) + bias[tid];
    out[(size_t)i * D_H + tid] = v;
}

// ---------------- launch ---------------------------------------------------
extern "C" void kernel_launch(void* const* d_in, const int* in_sizes, int n_in,
                              void* d_out, int out_size) {
    const float* adj  = (const float*)d_in[0];
    const float* feat = (const float*)d_in[1];
    const float* W0   = (const float*)d_in[2];
    const float* al0  = (const float*)d_in[3];
    const float* ar0  = (const float*)d_in[4];
    const float* b0   = (const float*)d_in[5];
    const float* W1   = (const float*)d_in[6];
    const float* al1  = (const float*)d_in[7];
    const float* ar1  = (const float*)d_in[8];
    const float* b1   = (const float*)d_in[9];
    const float* W2   = (const float*)d_in[10];
    const float* al2  = (const float*)d_in[11];
    const float* ar2  = (const float*)d_in[12];
    const float* b2   = (const float*)d_in[13];
    float* out = (float*)d_out;

    float *x, *h1, *h2;
    cudaGetSymbolAddress((void**)&x,  g_x);
    cudaGetSymbolAddress((void**)&h1, g_h1);
    cudaGetSymbolAddress((void**)&h2, g_h2);

    build_csr_kernel<<<N_NODES / 8, 256>>>(adj);

    const int gemm_grid = N_NODES / 16;   // 256 blocks

    // layer 0
    gemm_proj_kernel<<<gemm_grid, 128>>>(feat, W0, al0, ar0, x, HEADS);
    agg8_kernel<<<N_NODES, 128>>>(b0, h1, 1);

    // layer 1
    gemm_proj_kernel<<<gemm_grid, 128>>>(h1, W1, al1, ar1, x, HEADS);
    agg8_kernel<<<N_NODES, 128>>>(b1, h2, 1);

    // layer 2
    gemm_proj_kernel<<<gemm_grid, 128>>>(h2, W2, al2, ar2, x, 1);
    agg1_kernel<<<N_NODES, 64>>>(b2, out);
}

// round 5
// speedup vs baseline: 1.0734x; 1.0734x over previous
#include <cuda_runtime.h>
#include <math.h>

#define N_NODES 4096
#define KDIM    512
#define D_H     64
#define HEADS   8
#define MAXD    192
#define CH      64
#define KSPLIT  4
#define KS      128                 // K per split
#define GEMM_BLOCKS 1024            // 256 rowblocks * 4 splits
#define CSR_BLOCKS  1024            // 4 rows per block (4 warps)

typedef unsigned long long ull;

// ---------------- packed f32x2 helpers (Blackwell) ----------------
__device__ __forceinline__ ull pack2(float a) {
    ull r;
    asm("mov.b64 %0, {%1, %1};" : "=l"(r) : "f"(a));
    return r;
}
__device__ __forceinline__ void fma2(ull& d, ull a, ull b) {
    asm("fma.rn.f32x2 %0, %1, %2, %0;" : "+l"(d) : "l"(a), "l"(b));
}
__device__ __forceinline__ void unpack2(ull v, float& lo, float& hi) {
    asm("mov.b64 {%0, %1}, %2;" : "=f"(lo), "=f"(hi) : "l"(v));
}

// ---------------- scratch ----------------
__device__ float g_x [N_NODES * D_H];
__device__ float g_el[N_NODES * HEADS];
__device__ float g_er[N_NODES * HEADS];
__device__ float g_h1[N_NODES * D_H * HEADS];
__device__ float g_h2[N_NODES * D_H * HEADS];
__device__ float g_part[KSPLIT * N_NODES * D_H];   // split-K partials (4 MB)
__device__ int   g_cols[N_NODES * MAXD];
__device__ int   g_deg [N_NODES];

// ---- split-K GEMM (+ optional fused CSR build in extra blocks) -----------
// gemm blocks [0, GEMM_BLOCKS): rowblock = bx>>2 (16 rows), split = bx&3 (K=128).
// csr blocks  [GEMM_BLOCKS, +CSR_BLOCKS): 4 warps, warp per adjacency row.
__global__ __launch_bounds__(128) void gemm_csr_kernel(const float* __restrict__ adj,
                                                       const float* __restrict__ A,
                                                       const float* __restrict__ B) {
    if (blockIdx.x >= GEMM_BLOCKS) {
        // ---------------- CSR build ----------------
        int warp = (blockIdx.x - GEMM_BLOCKS) * 4 + (threadIdx.x >> 5);
        int lane = threadIdx.x & 31;
        const float4* a = reinterpret_cast<const float4*>(adj + (size_t)warp * N_NODES);
        int* outc = g_cols + warp * MAXD;
        int base = 0;
        for (int j0 = 0; j0 < N_NODES; j0 += 128) {
            float4 v = a[(j0 >> 2) + lane];
            float vv[4] = {v.x, v.y, v.z, v.w};
            #pragma unroll
            for (int c = 0; c < 4; c++) {
                unsigned m = __ballot_sync(0xffffffffu, vv[c] != 0.0f);
                if (vv[c] != 0.0f) {
                    int pos = base + __popc(m & ((1u << lane) - 1u));
                    if (pos < MAXD) outc[pos] = j0 + lane * 4 + c;
                }
                base += __popc(m);
            }
        }
        if (lane == 0) g_deg[warp] = base < MAXD ? base : MAXD;
        return;
    }

    // ---------------- GEMM partial: rows 16, K slice 128 ----------------
    __shared__ float As[16][33];
    __shared__ float Bs[32][64];
    int tid = threadIdx.x;
    int tx = tid & 15, ty = tid >> 4;
    int rowBase = (blockIdx.x >> 2) * 16;
    int split   = blockIdx.x & 3;
    int k0      = split * KS;

    int arow = tid >> 3;
    int ak4  = (tid & 7) << 2;
    const float* Aptr = A + (size_t)(rowBase + arow) * KDIM + k0 + ak4;

    float4 a_n, b_n[4];
    a_n = *reinterpret_cast<const float4*>(Aptr);
    #pragma unroll
    for (int s = 0; s < 4; s++) {
        int idx = tid + 128 * s;
        b_n[s] = *reinterpret_cast<const float4*>(B + (size_t)(k0 + (idx >> 4)) * 64 + (idx & 15) * 4);
    }

    ull acc[2][2] = {{0ull, 0ull}, {0ull, 0ull}};

    for (int kt = 0; kt < KS; kt += 32) {
        As[arow][ak4+0] = a_n.x; As[arow][ak4+1] = a_n.y;
        As[arow][ak4+2] = a_n.z; As[arow][ak4+3] = a_n.w;
        #pragma unroll
        for (int s = 0; s < 4; s++) {
            int idx = tid + 128 * s;
            *reinterpret_cast<float4*>(&Bs[idx >> 4][(idx & 15) * 4]) = b_n[s];
        }
        __syncthreads();
        if (kt + 32 < KS) {
            a_n = *reinterpret_cast<const float4*>(Aptr + kt + 32);
            #pragma unroll
            for (int s = 0; s < 4; s++) {
                int idx = tid + 128 * s;
                b_n[s] = *reinterpret_cast<const float4*>(B + (size_t)(k0 + kt + 32 + (idx >> 4)) * 64 + (idx & 15) * 4);
            }
        }
        #pragma unroll
        for (int k = 0; k < 32; k++) {
            ull pa0 = pack2(As[ty*2][k]);
            ull pa1 = pack2(As[ty*2+1][k]);
            ulonglong2 bb = *reinterpret_cast<const ulonglong2*>(&Bs[k][tx*4]);
            fma2(acc[0][0], pa0, bb.x);
            fma2(acc[0][1], pa0, bb.y);
            fma2(acc[1][0], pa1, bb.x);
            fma2(acc[1][1], pa1, bb.y);
        }
        __syncthreads();
    }

    float* P = g_part + (size_t)split * (N_NODES * D_H);
    #pragma unroll
    for (int i = 0; i < 2; i++) {
        int r = rowBase + ty*2 + i;
        ulonglong2 v; v.x = acc[i][0]; v.y = acc[i][1];
        *reinterpret_cast<ulonglong2*>(P + (size_t)r * 64 + tx*4) = v;
    }
}

// ---- reduce split-K partials (fixed order) + el/er projection ------------
// 256 threads = 4 rows x 64 d. grid = 1024.
__global__ __launch_bounds__(256) void reduce_proj_kernel(const float* __restrict__ al,
                                                          const float* __restrict__ ar,
                                                          float* __restrict__ X, int H) {
    __shared__ float sC[4][64];
    __shared__ float sAl[512];
    __shared__ float sAr[512];
    int tid = threadIdx.x;
    int r = tid >> 6, d = tid & 63;
    int row = blockIdx.x * 4 + r;
    size_t off = (size_t)row * 64 + d;
    const size_t SZ = (size_t)N_NODES * D_H;
    float v = ((g_part[off] + g_part[SZ + off]) + (g_part[2*SZ + off] + g_part[3*SZ + off]));
    X[off] = v;
    sC[r][d] = v;
    for (int idx = tid; idx < 64 * H; idx += 256) {
        sAl[idx] = al[idx];
        sAr[idx] = ar[idx];
    }
    __syncthreads();
    if (tid < 4 * H) {
        int rr = (H == 8) ? (tid >> 3) : tid;
        int h  = (H == 8) ? (tid & 7)  : 0;
        float sl = 0.f, sr = 0.f;
        #pragma unroll
        for (int dd = 0; dd < 64; dd++) {
            float cv = sC[rr][dd];
            sl += cv * sAl[dd * H + h];
            sr += cv * sAr[dd * H + h];
        }
        g_el[(blockIdx.x * 4 + rr) * H + h] = sl;
        g_er[(blockIdx.x * 4 + rr) * H + h] = sr;
    }
}

// ---------------- 8-head aggregation: block per node, 128 threads ----------
__global__ __launch_bounds__(128) void agg8_kernel(const float* __restrict__ bias,
                                                   float* __restrict__ out, int act) {
    int i   = blockIdx.x;
    int tid = threadIdx.x;
    int h   = tid >> 4;
    int q   = tid & 15;

    __shared__ int   s_cols[CH];
    __shared__ float s_el[HEADS];
    __shared__ ull   s_w[CH][HEADS];

    if (tid < HEADS) s_el[tid] = g_el[i * HEADS + tid];
    int deg = g_deg[i];
    const int* cols = g_cols + (size_t)i * MAXD;
    const float* xq = g_x + q * 4;

    ull acc0 = 0ull, acc1 = 0ull;
    float sw = 0.f;

    for (int j0 = 0; j0 < deg; j0 += CH) {
        int cl = min(CH, deg - j0);
        if (tid < cl) s_cols[tid] = cols[j0 + tid];
        __syncthreads();
        for (int idx = tid; idx < cl * HEADS; idx += 128) {
            int jj = idx >> 3, hh = idx & 7;
            float s = s_el[hh] + g_er[s_cols[jj] * HEADS + hh];
            s = (s >= 0.f) ? s : 0.2f * s;
            s_w[jj][hh] = pack2(__expf(s));
        }
        __syncthreads();
        #pragma unroll 4
        for (int jj = 0; jj < cl; jj++) {
            ull pw = s_w[jj][h];
            ulonglong2 xv = *reinterpret_cast<const ulonglong2*>(xq + (size_t)s_cols[jj] * D_H);
            float wlo, whi;
            unpack2(pw, wlo, whi);
            fma2(acc0, pw, xv.x);
            fma2(acc1, pw, xv.y);
            sw += wlo;
        }
        __syncthreads();
    }

    float inv = 1.0f / fmaxf(sw, 1e-12f);
    float4 bv = *reinterpret_cast<const float4*>(bias + q * 4);
    float v0, v1, v2, v3;
    unpack2(acc0, v0, v1);
    unpack2(acc1, v2, v3);
    v0 = v0 * inv + bv.x; v1 = v1 * inv + bv.y;
    v2 = v2 * inv + bv.z; v3 = v3 * inv + bv.w;
    if (act) {
        v0 = (v0 > 0.f) ? v0 : expm1f(v0);
        v1 = (v1 > 0.f) ? v1 : expm1f(v1);
        v2 = (v2 > 0.f) ? v2 : expm1f(v2);
        v3 = (v3 > 0.f) ? v3 : expm1f(v3);
    }
    float4 ov = make_float4(v0, v1, v2, v3);
    *reinterpret_cast<float4*>(out + (size_t)i * (HEADS * D_H) + h * D_H + q * 4) = ov;
}

// ---------------- 1-head aggregation: block per node, 64 threads -----------
__global__ __launch_bounds__(64) void agg1_kernel(const float* __restrict__ bias,
                                                  float* __restrict__ out) {
    int i   = blockIdx.x;
    int tid = threadIdx.x;   // = d

    __shared__ int   s_cols[CH];
    __shared__ float s_w[CH];

    float eli = g_el[i];
    int deg = g_deg[i];
    const int* cols = g_cols + (size_t)i * MAXD;
    float acc = 0.f, sw = 0.f;

    for (int j0 = 0; j0 < deg; j0 += CH) {
        int cl = min(CH, deg - j0);
        if (tid < cl) {
            int c = cols[j0 + tid];
            s_cols[tid] = c;
            float s = eli + g_er[c];
            s = (s >= 0.f) ? s : 0.2f * s;
            s_w[tid] = __expf(s);
        }
        __syncthreads();
        #pragma unroll 4
        for (int jj = 0; jj < cl; jj++) {
            float wv = s_w[jj];
            acc += wv * g_x[(size_t)s_cols[jj] * D_H + tid];
            sw  += wv;
        }
        __syncthreads();
    }

    float v = acc / fmaxf(sw, 1e-12f) + bias[tid];
    out[(size_t)i * D_H + tid] = v;
}

// ---------------- launch ---------------------------------------------------
extern "C" void kernel_launch(void* const* d_in, const int* in_sizes, int n_in,
                              void* d_out, int out_size) {
    const float* adj  = (const float*)d_in[0];
    const float* feat = (const float*)d_in[1];
    const float* W0   = (const float*)d_in[2];
    const float* al0  = (const float*)d_in[3];
    const float* ar0  = (const float*)d_in[4];
    const float* b0   = (const float*)d_in[5];
    const float* W1   = (const float*)d_in[6];
    const float* al1  = (const float*)d_in[7];
    const float* ar1  = (const float*)d_in[8];
    const float* b1   = (const float*)d_in[9];
    const float* W2   = (const float*)d_in[10];
    const float* al2  = (const float*)d_in[11];
    const float* ar2  = (const float*)d_in[12];
    const float* b2   = (const float*)d_in[13];
    float* out = (float*)d_out;

    float *x, *h1, *h2;
    cudaGetSymbolAddress((void**)&x,  g_x);
    cudaGetSymbolAddress((void**)&h1, g_h1);
    cudaGetSymbolAddress((void**)&h2, g_h2);

    // layer 0 (CSR build fused into the GEMM launch as extra blocks)
    gemm_csr_kernel<<<GEMM_BLOCKS + CSR_BLOCKS, 128>>>(adj, feat, W0);
    reduce_proj_kernel<<<N_NODES / 4, 256>>>(al0, ar0, x, HEADS);
    agg8_kernel<<<N_NODES, 128>>>(b0, h1, 1);

    // layer 1
    gemm_csr_kernel<<<GEMM_BLOCKS, 128>>>(adj, h1, W1);
    reduce_proj_kernel<<<N_NODES / 4, 256>>>(al1, ar1, x, HEADS);
    agg8_kernel<<<N_NODES, 128>>>(b1, h2, 1);

    // layer 2
    gemm_csr_kernel<<<GEMM_BLOCKS, 128>>>(adj, h2, W2);
    reduce_proj_kernel<<<N_NODES / 4, 256>>>(al2, ar2, x, 1);
    agg1_kernel<<<N_NODES, 64>>>(b2, out);
}

// round 6
// speedup vs baseline: 1.0738x; 1.0003x over previous
#include <cuda_runtime.h>
#include <math.h>

#define N_NODES 4096
#define KDIM    512
#define D_H     64
#define HEADS   8
#define MAXD    192
#define CH      64
#define KSPLIT  8
#define KS      64                  // K per split
#define BM      32
#define ROWBLKS (N_NODES / BM)      // 128
#define GEMM_BLOCKS (ROWBLKS * KSPLIT)  // 1024
#define CSR_BLOCKS  1024

typedef unsigned long long ull;

// ---------------- packed f32x2 helpers (Blackwell) ----------------
__device__ __forceinline__ ull pack2(float a) {
    ull r;
    asm("mov.b64 %0, {%1, %1};" : "=l"(r) : "f"(a));
    return r;
}
__device__ __forceinline__ void fma2(ull& d, ull a, ull b) {
    asm("fma.rn.f32x2 %0, %1, %2, %0;" : "+l"(d) : "l"(a), "l"(b));
}
__device__ __forceinline__ void unpack2(ull v, float& lo, float& hi) {
    asm("mov.b64 {%0, %1}, %2;" : "=f"(lo), "=f"(hi) : "l"(v));
}

// ---------------- scratch ----------------
__device__ float g_x [N_NODES * D_H];
__device__ float g_el[N_NODES * HEADS];
__device__ float g_er[N_NODES * HEADS];
__device__ float g_h1[N_NODES * D_H * HEADS];
__device__ float g_h2[N_NODES * D_H * HEADS];
__device__ float g_part[KSPLIT * N_NODES * D_H];   // 8 MB split-K partials
__device__ int   g_cols[N_NODES * MAXD];
__device__ int   g_deg [N_NODES];

// ---- split-K GEMM (+ fused CSR build in extra blocks) --------------------
// gemm blocks [0, GEMM_BLOCKS): rowblock = bx>>3 (32 rows), split = bx&7 (K=64).
// csr blocks  [GEMM_BLOCKS, +CSR_BLOCKS): 4 warps, warp per adjacency row.
__global__ __launch_bounds__(128) void gemm_csr_kernel(const float* __restrict__ adj,
                                                       const float* __restrict__ A,
                                                       const float* __restrict__ B) {
    if (blockIdx.x >= GEMM_BLOCKS) {
        // ---------------- CSR build ----------------
        int warp = (blockIdx.x - GEMM_BLOCKS) * 4 + (threadIdx.x >> 5);
        int lane = threadIdx.x & 31;
        const float4* a = reinterpret_cast<const float4*>(adj + (size_t)warp * N_NODES);
        int* outc = g_cols + warp * MAXD;
        int base = 0;
        for (int j0 = 0; j0 < N_NODES; j0 += 128) {
            float4 v = a[(j0 >> 2) + lane];
            float vv[4] = {v.x, v.y, v.z, v.w};
            #pragma unroll
            for (int c = 0; c < 4; c++) {
                unsigned m = __ballot_sync(0xffffffffu, vv[c] != 0.0f);
                if (vv[c] != 0.0f) {
                    int pos = base + __popc(m & ((1u << lane) - 1u));
                    if (pos < MAXD) outc[pos] = j0 + lane * 4 + c;
                }
                base += __popc(m);
            }
        }
        if (lane == 0) g_deg[warp] = base < MAXD ? base : MAXD;
        return;
    }

    // ------- GEMM partial: 32 rows x 64 cols, K slice 64, 4x4 micro-tile ---
    __shared__ float AsT[32][36];   // [k][row], row XOR-swizzled in groups of 4
    __shared__ float Bs[32][64];
    int tid = threadIdx.x;
    int tx = tid & 15, ty = tid >> 4;       // ty 0..7 -> rows ty*4..ty*4+3
    int rowBase = (blockIdx.x >> 3) * BM;
    int k0      = (blockIdx.x & 7) * KS;

    // A: 2 float4 per thread; idx = tid + 128*s -> row = idx>>3, kk = (idx&7)*4
    // B: 4 float4 per thread; idx = tid + 128*s -> brow = idx>>4, bc = (idx&15)*4
    float4 a_n[2], b_n[4];
    #pragma unroll
    for (int s = 0; s < 2; s++) {
        int idx = tid + 128 * s;
        a_n[s] = *reinterpret_cast<const float4*>(
            A + (size_t)(rowBase + (idx >> 3)) * KDIM + k0 + ((idx & 7) << 2));
    }
    #pragma unroll
    for (int s = 0; s < 4; s++) {
        int idx = tid + 128 * s;
        b_n[s] = *reinterpret_cast<const float4*>(
            B + (size_t)(k0 + (idx >> 4)) * 64 + ((idx & 15) << 2));
    }

    ull acc[4][2] = {{0,0},{0,0},{0,0},{0,0}};

    for (int kt = 0; kt < KS; kt += 32) {
        // stage A transposed with swizzle: elem row r at k stored at r ^ (((k>>3)&3)<<2)
        #pragma unroll
        for (int s = 0; s < 2; s++) {
            int idx = tid + 128 * s;
            int row = idx >> 3;
            int kk  = (idx & 7) << 2;
            float av[4] = {a_n[s].x, a_n[s].y, a_n[s].z, a_n[s].w};
            #pragma unroll
            for (int i = 0; i < 4; i++) {
                int k = kk + i;
                AsT[k][row ^ ((( k >> 3) & 3) << 2)] = av[i];
            }
        }
        #pragma unroll
        for (int s = 0; s < 4; s++) {
            int idx = tid + 128 * s;
            *reinterpret_cast<float4*>(&Bs[idx >> 4][(idx & 15) << 2]) = b_n[s];
        }
        __syncthreads();
        if (kt + 32 < KS) {
            #pragma unroll
            for (int s = 0; s < 2; s++) {
                int idx = tid + 128 * s;
                a_n[s] = *reinterpret_cast<const float4*>(
                    A + (size_t)(rowBase + (idx >> 3)) * KDIM + k0 + kt + 32 + ((idx & 7) << 2));
            }
            #pragma unroll
            for (int s = 0; s < 4; s++) {
                int idx = tid + 128 * s;
                b_n[s] = *reinterpret_cast<const float4*>(
                    B + (size_t)(k0 + kt + 32 + (idx >> 4)) * 64 + ((idx & 15) << 2));
            }
        }
        #pragma unroll
        for (int k = 0; k < 32; k++) {
            int sr = (ty ^ ((k >> 3) & 3)) << 2;                 // swizzled 4-row base
            float4 av = *reinterpret_cast<const float4*>(&AsT[k][sr]);
            ulonglong2 bb = *reinterpret_cast<const ulonglong2*>(&Bs[k][tx * 4]);
            ull pa0 = pack2(av.x), pa1 = pack2(av.y), pa2 = pack2(av.z), pa3 = pack2(av.w);
            fma2(acc[0][0], pa0, bb.x); fma2(acc[0][1], pa0, bb.y);
            fma2(acc[1][0], pa1, bb.x); fma2(acc[1][1], pa1, bb.y);
            fma2(acc[2][0], pa2, bb.x); fma2(acc[2][1], pa2, bb.y);
            fma2(acc[3][0], pa3, bb.x); fma2(acc[3][1], pa3, bb.y);
        }
        __syncthreads();
    }

    float* P = g_part + (size_t)(blockIdx.x & 7) * (N_NODES * D_H);
    #pragma unroll
    for (int i = 0; i < 4; i++) {
        int r = rowBase + ty * 4 + i;
        ulonglong2 v; v.x = acc[i][0]; v.y = acc[i][1];
        *reinterpret_cast<ulonglong2*>(P + (size_t)r * 64 + tx * 4) = v;
    }
}

// ---- reduce 8 split-K partials (fixed order) + el/er projection ----------
// 256 threads = 4 rows x 64 d. grid = 1024.
__global__ __launch_bounds__(256) void reduce_proj_kernel(const float* __restrict__ al,
                                                          const float* __restrict__ ar,
                                                          float* __restrict__ X, int H) {
    __shared__ float sC[4][64];
    __shared__ float sAl[512];
    __shared__ float sAr[512];
    int tid = threadIdx.x;
    int r = tid >> 6, d = tid & 63;
    int row = blockIdx.x * 4 + r;
    size_t off = (size_t)row * 64 + d;
    const size_t SZ = (size_t)N_NODES * D_H;
    float p0 = g_part[off]          + g_part[SZ + off];
    float p1 = g_part[2*SZ + off]   + g_part[3*SZ + off];
    float p2 = g_part[4*SZ + off]   + g_part[5*SZ + off];
    float p3 = g_part[6*SZ + off]   + g_part[7*SZ + off];
    float v = (p0 + p1) + (p2 + p3);
    X[off] = v;
    sC[r][d] = v;
    for (int idx = tid; idx < 64 * H; idx += 256) {
        sAl[idx] = al[idx];
        sAr[idx] = ar[idx];
    }
    __syncthreads();
    if (tid < 4 * H) {
        int rr = (H == 8) ? (tid >> 3) : tid;
        int h  = (H == 8) ? (tid & 7)  : 0;
        float sl = 0.f, sr = 0.f;
        #pragma unroll
        for (int dd = 0; dd < 64; dd++) {
            float cv = sC[rr][dd];
            sl += cv * sAl[dd * H + h];
            sr += cv * sAr[dd * H + h];
        }
        g_el[(blockIdx.x * 4 + rr) * H + h] = sl;
        g_er[(blockIdx.x * 4 + rr) * H + h] = sr;
    }
}

// ---------------- 8-head aggregation: block per node, 128 threads ----------
// thread = (h, q); batched (MLP=4) LDG gather of x rows.
__global__ __launch_bounds__(128) void agg8_kernel(const float* __restrict__ bias,
                                                   float* __restrict__ out, int act) {
    int i   = blockIdx.x;
    int tid = threadIdx.x;
    int h   = tid >> 4;
    int q   = tid & 15;

    __shared__ int   s_cols[CH];
    __shared__ float s_el[HEADS];
    __shared__ ull   s_w[CH][HEADS];

    if (tid < HEADS) s_el[tid] = g_el[i * HEADS + tid];
    int deg = g_deg[i];
    const int* cols = g_cols + (size_t)i * MAXD;
    const float* xq = g_x + q * 4;

    ull acc0 = 0ull, acc1 = 0ull;
    float sw = 0.f;

    for (int j0 = 0; j0 < deg; j0 += CH) {
        int cl = min(CH, deg - j0);
        if (tid < cl) s_cols[tid] = cols[j0 + tid];
        __syncthreads();
        for (int idx = tid; idx < cl * HEADS; idx += 128) {
            int jj = idx >> 3, hh = idx & 7;
            float s = s_el[hh] + g_er[s_cols[jj] * HEADS + hh];
            s = (s >= 0.f) ? s : 0.2f * s;
            s_w[jj][hh] = pack2(__expf(s));
        }
        __syncthreads();
        int jj = 0;
        for (; jj + 4 <= cl; jj += 4) {
            int c0 = s_cols[jj], c1 = s_cols[jj+1], c2 = s_cols[jj+2], c3 = s_cols[jj+3];
            ulonglong2 x0 = *reinterpret_cast<const ulonglong2*>(xq + (size_t)c0 * D_H);
            ulonglong2 x1 = *reinterpret_cast<const ulonglong2*>(xq + (size_t)c1 * D_H);
            ulonglong2 x2 = *reinterpret_cast<const ulonglong2*>(xq + (size_t)c2 * D_H);
            ulonglong2 x3 = *reinterpret_cast<const ulonglong2*>(xq + (size_t)c3 * D_H);
            ull w0 = s_w[jj][h], w1 = s_w[jj+1][h], w2 = s_w[jj+2][h], w3 = s_w[jj+3][h];
            fma2(acc0, w0, x0.x); fma2(acc1, w0, x0.y);
            fma2(acc0, w1, x1.x); fma2(acc1, w1, x1.y);
            fma2(acc0, w2, x2.x); fma2(acc1, w2, x2.y);
            fma2(acc0, w3, x3.x); fma2(acc1, w3, x3.y);
            float l0, l1, l2, l3, dmy;
            unpack2(w0, l0, dmy); unpack2(w1, l1, dmy);
            unpack2(w2, l2, dmy); unpack2(w3, l3, dmy);
            sw += (l0 + l1) + (l2 + l3);
        }
        for (; jj < cl; jj++) {
            ull pw = s_w[jj][h];
            ulonglong2 xv = *reinterpret_cast<const ulonglong2*>(xq + (size_t)s_cols[jj] * D_H);
            fma2(acc0, pw, xv.x); fma2(acc1, pw, xv.y);
            float wlo, dmy; unpack2(pw, wlo, dmy);
            sw += wlo;
        }
        __syncthreads();
    }

    float inv = 1.0f / fmaxf(sw, 1e-12f);
    float4 bv = *reinterpret_cast<const float4*>(bias + q * 4);
    float v0, v1, v2, v3;
    unpack2(acc0, v0, v1);
    unpack2(acc1, v2, v3);
    v0 = v0 * inv + bv.x; v1 = v1 * inv + bv.y;
    v2 = v2 * inv + bv.z; v3 = v3 * inv + bv.w;
    if (act) {
        v0 = (v0 > 0.f) ? v0 : expm1f(v0);
        v1 = (v1 > 0.f) ? v1 : expm1f(v1);
        v2 = (v2 > 0.f) ? v2 : expm1f(v2);
        v3 = (v3 > 0.f) ? v3 : expm1f(v3);
    }
    float4 ov = make_float4(v0, v1, v2, v3);
    *reinterpret_cast<float4*>(out + (size_t)i * (HEADS * D_H) + h * D_H + q * 4) = ov;
}

// ---------------- 1-head aggregation: block per node, 64 threads -----------
__global__ __launch_bounds__(64) void agg1_kernel(const float* __restrict__ bias,
                                                  float* __restrict__ out) {
    int i   = blockIdx.x;
    int tid = threadIdx.x;   // = d

    __shared__ int   s_cols[CH];
    __shared__ float s_w[CH];

    float eli = g_el[i];
    int deg = g_deg[i];
    const int* cols = g_cols + (size_t)i * MAXD;
    float acc = 0.f, sw = 0.f;

    for (int j0 = 0; j0 < deg; j0 += CH) {
        int cl = min(CH, deg - j0);
        if (tid < cl) {
            int c = cols[j0 + tid];
            s_cols[tid] = c;
            float s = eli + g_er[c];
            s = (s >= 0.f) ? s : 0.2f * s;
            s_w[tid] = __expf(s);
        }
        __syncthreads();
        int jj = 0;
        for (; jj + 4 <= cl; jj += 4) {
            int c0 = s_cols[jj], c1 = s_cols[jj+1], c2 = s_cols[jj+2], c3 = s_cols[jj+3];
            float x0 = g_x[(size_t)c0 * D_H + tid];
            float x1 = g_x[(size_t)c1 * D_H + tid];
            float x2 = g_x[(size_t)c2 * D_H + tid];
            float x3 = g_x[(size_t)c3 * D_H + tid];
            float w0 = s_w[jj], w1 = s_w[jj+1], w2 = s_w[jj+2], w3 = s_w[jj+3];
            acc += w0*x0; acc += w1*x1; acc += w2*x2; acc += w3*x3;
            sw  += (w0 + w1) + (w2 + w3);
        }
        for (; jj < cl; jj++) {
            float wv = s_w[jj];
            acc += wv * g_x[(size_t)s_cols[jj] * D_H + tid];
            sw  += wv;
        }
        __syncthreads();
    }

    float v = acc / fmaxf(sw, 1e-12f) + bias[tid];
    out[(size_t)i * D_H + tid] = v;
}

// ---------------- launch ---------------------------------------------------
extern "C" void kernel_launch(void* const* d_in, const int* in_sizes, int n_in,
                              void* d_out, int out_size) {
    const float* adj  = (const float*)d_in[0];
    const float* feat = (const float*)d_in[1];
    const float* W0   = (const float*)d_in[2];
    const float* al0  = (const float*)d_in[3];
    const float* ar0  = (const float*)d_in[4];
    const float* b0   = (const float*)d_in[5];
    const float* W1   = (const float*)d_in[6];
    const float* al1  = (const float*)d_in[7];
    const float* ar1  = (const float*)d_in[8];
    const float* b1   = (const float*)d_in[9];
    const float* W2   = (const float*)d_in[10];
    const float* al2  = (const float*)d_in[11];
    const float* ar2  = (const float*)d_in[12];
    const float* b2   = (const float*)d_in[13];
    float* out = (float*)d_out;

    float *x, *h1, *h2;
    cudaGetSymbolAddress((void**)&x,  g_x);
    cudaGetSymbolAddress((void**)&h1, g_h1);
    cudaGetSymbolAddress((void**)&h2, g_h2);

    // layer 0 (CSR build fused into the GEMM launch as extra blocks)
    gemm_csr_kernel<<<GEMM_BLOCKS + CSR_BLOCKS, 128>>>(adj, feat, W0);
    reduce_proj_kernel<<<N_NODES / 4, 256>>>(al0, ar0, x, HEADS);
    agg8_kernel<<<N_NODES, 128>>>(b0, h1, 1);

    // layer 1
    gemm_csr_kernel<<<GEMM_BLOCKS, 128>>>(adj, h1, W1);
    reduce_proj_kernel<<<N_NODES / 4, 256>>>(al1, ar1, x, HEADS);
    agg8_kernel<<<N_NODES, 128>>>(b1, h2, 1);

    // layer 2
    gemm_csr_kernel<<<GEMM_BLOCKS, 128>>>(adj, h2, W2);
    reduce_proj_kernel<<<N_NODES / 4, 256>>>(al2, ar2, x, 1);
    agg1_kernel<<<N_NODES, 64>>>(b2, out);
}